// round 15
// baseline (speedup 1.0000x reference)
#include <cuda_runtime.h>
#include <cuda_fp16.h>
#include <cstdint>

#define KCH 2
#define NNODES 100000
#define ZD 128
#define FD 128
#define ROWS_TOTAL (KCH * NNODES)   // 200000
#define EDGES_MAX 1600000
#define NCHUNK ((NNODES + 1023) / 1024)   // 98

// ---------------- scratch (static device globals; zero-initialized) --------
__device__ __half g_support[(size_t)ROWS_TOTAL * FD];  // 51.2 MB (fp16)
__device__ __half g_wh[FD * ZD];                       // W^T fp16 [f][k]
__device__ int   g_count[NNODES];                      // starts 0; scan resets
__device__ int   g_rowstart[NNODES + 1];
__device__ int   g_cursor[NNODES];
__device__ unsigned long long g_scanstate[NCHUNK];     // starts 0; spmm resets
__device__ int2  g_csr[EDGES_MAX];                     // (col, val bits)

// ======================= hist (ILP-8) + W convert ===========================
__global__ __launch_bounds__(256) void hist_w_kernel(
    const int* __restrict__ rows, const float* __restrict__ w, int E, int nhist) {
    const int tid = threadIdx.x;
    if (blockIdx.x >= nhist) {
        int base = ((blockIdx.x - nhist) * 256 + tid) * 4;
#pragma unroll
        for (int j = 0; j < 4; ++j) {
            int i = base + j;
            if (i < FD * ZD) {
                int f = i >> 7, k = i & 127;
                g_wh[i] = __float2half_rn(w[k * FD + f]);   // g_wh[f][k]=W[k][f]
            }
        }
        return;
    }
    const int e = (blockIdx.x * 256 + tid) * 8;
    if (e + 7 < E) {
        int4 r0 = *(const int4*)(rows + e);
        int4 r1 = *(const int4*)(rows + e + 4);
        atomicAdd(&g_count[r0.x], 1);
        atomicAdd(&g_count[r0.y], 1);
        atomicAdd(&g_count[r0.z], 1);
        atomicAdd(&g_count[r0.w], 1);
        atomicAdd(&g_count[r1.x], 1);
        atomicAdd(&g_count[r1.y], 1);
        atomicAdd(&g_count[r1.z], 1);
        atomicAdd(&g_count[r1.w], 1);
    } else {
        for (int j = e; j < E; ++j) atomicAdd(&g_count[rows[j]], 1);
    }
}

// fused scan: per-chunk inclusive scan + single-wave lookback; resets g_count
__global__ __launch_bounds__(1024) void scan_fused_kernel(int E) {
    __shared__ int s[1024];
    __shared__ int s_pref;
    const int t = threadIdx.x;
    const int b = blockIdx.x;
    const int idx = b * 1024 + t;
    const int v = (idx < NNODES) ? g_count[idx] : 0;
    s[t] = v;
    __syncthreads();
#pragma unroll
    for (int off = 1; off < 1024; off <<= 1) {
        int add = (t >= off) ? s[t - off] : 0;
        __syncthreads();
        s[t] += add;
        __syncthreads();
    }
    const int incl = s[t];
    if (t == 1023)
        atomicExch(&g_scanstate[b], (1ULL << 63) | (unsigned long long)s[1023]);

    if (t < 32) {
        unsigned int partial = 0;
        for (int base = 0; base < b; base += 32) {
            int j = base + t;
            unsigned int tot = 0;
            if (j < b) {
                unsigned long long w;
                do { w = atomicAdd(&g_scanstate[j], 0ULL); } while (!(w >> 63));
                tot = (unsigned int)w;
            }
            partial += tot;
        }
#pragma unroll
        for (int o = 16; o > 0; o >>= 1)
            partial += __shfl_down_sync(0xFFFFFFFFu, partial, o);
        if (t == 0) s_pref = (int)partial;
    }
    __syncthreads();
    const int excl = s_pref + incl - v;
    if (idx < NNODES) {
        g_rowstart[idx] = excl;
        g_cursor[idx]   = excl;
        g_count[idx]    = 0;    // reset for next graph replay
    }
    if (b == NCHUNK - 1 && t == 0) g_rowstart[NNODES] = E;
}

// ======================= fused GEMM + scatter (R7 structure) =================
#define XSTR 136
#define SMEM_GEMM_BYTES (2 * 128 * XSTR * 2)   // 69632

static __device__ __forceinline__ void ldsm_x4(uint32_t* r, uint32_t addr) {
    asm volatile("ldmatrix.sync.aligned.m8n8.x4.shared.b16 {%0,%1,%2,%3}, [%4];"
                 : "=r"(r[0]), "=r"(r[1]), "=r"(r[2]), "=r"(r[3]) : "r"(addr));
}

static __device__ __forceinline__ void mma_f16(float* d, const uint32_t* a,
                                               const uint32_t* b) {
    asm volatile(
        "mma.sync.aligned.m16n8k16.row.col.f32.f16.f16.f32 "
        "{%0,%1,%2,%3}, {%4,%5,%6,%7}, {%8,%9}, {%0,%1,%2,%3};\n"
        : "+f"(d[0]), "+f"(d[1]), "+f"(d[2]), "+f"(d[3])
        : "r"(a[0]), "r"(a[1]), "r"(a[2]), "r"(a[3]), "r"(b[0]), "r"(b[1]));
}

__global__ __launch_bounds__(256, 2) void gemm_scatter_kernel(
    const float* __restrict__ x,
    const int* __restrict__ rows, const int* __restrict__ cols,
    const float* __restrict__ vals, int E, int ngemm) {
    extern __shared__ __half smh[];
    const int tid = threadIdx.x;

    if (blockIdx.x >= ngemm) {
        // ---------------- scatter path (ILP-8) ----------------
        const int e = ((blockIdx.x - ngemm) * 256 + tid) * 8;
        if (e + 7 < E) {
            int4 r0 = *(const int4*)(rows + e);
            int4 r1 = *(const int4*)(rows + e + 4);
            int4 c0 = *(const int4*)(cols + e);
            int4 c1 = *(const int4*)(cols + e + 4);
            float4 v0 = *(const float4*)(vals + e);
            float4 v1 = *(const float4*)(vals + e + 4);
            int p0 = atomicAdd(&g_cursor[r0.x], 1);
            int p1 = atomicAdd(&g_cursor[r0.y], 1);
            int p2 = atomicAdd(&g_cursor[r0.z], 1);
            int p3 = atomicAdd(&g_cursor[r0.w], 1);
            int p4 = atomicAdd(&g_cursor[r1.x], 1);
            int p5 = atomicAdd(&g_cursor[r1.y], 1);
            int p6 = atomicAdd(&g_cursor[r1.z], 1);
            int p7 = atomicAdd(&g_cursor[r1.w], 1);
            g_csr[p0] = make_int2(c0.x, __float_as_int(v0.x));
            g_csr[p1] = make_int2(c0.y, __float_as_int(v0.y));
            g_csr[p2] = make_int2(c0.z, __float_as_int(v0.z));
            g_csr[p3] = make_int2(c0.w, __float_as_int(v0.w));
            g_csr[p4] = make_int2(c1.x, __float_as_int(v1.x));
            g_csr[p5] = make_int2(c1.y, __float_as_int(v1.y));
            g_csr[p6] = make_int2(c1.z, __float_as_int(v1.z));
            g_csr[p7] = make_int2(c1.w, __float_as_int(v1.w));
        } else {
            for (int j = e; j < E; ++j) {
                int p = atomicAdd(&g_cursor[rows[j]], 1);
                g_csr[p] = make_int2(cols[j], __float_as_int(vals[j]));
            }
        }
        return;
    }

    // ---------------- GEMM path ----------------
    __half* Xh = smh;                    // [128][XSTR]
    __half* Wh = smh + 128 * XSTR;       // [f][XSTR]
    const int lane = tid & 31;
    const int wid = tid >> 5;
    const long rowbase = (long)blockIdx.x * 128;

#pragma unroll
    for (int it = 0; it < 16; ++it) {
        int id4 = tid + it * 256;
        int rr = id4 >> 5;
        int q = (id4 & 31) << 2;
        long grow = rowbase + rr;
        float4 vv = make_float4(0.f, 0.f, 0.f, 0.f);
        if (grow < ROWS_TOTAL) vv = *(const float4*)(x + grow * ZD + q);
        __half2* dst = (__half2*)(Xh + rr * XSTR + q);
        dst[0] = __floats2half2_rn(vv.x, vv.y);
        dst[1] = __floats2half2_rn(vv.z, vv.w);
    }
#pragma unroll
    for (int it = 0; it < 8; ++it) {
        int idx = tid + it * 256;
        int f = idx >> 4;
        int seg = (idx & 15) << 3;
        *(uint4*)(Wh + f * XSTR + seg) = *(const uint4*)(g_wh + f * ZD + seg);
    }
    __syncthreads();

    const int wm = wid >> 1;
    const int wn = wid & 1;

    float acc[2][8][4];
#pragma unroll
    for (int mt = 0; mt < 2; ++mt)
#pragma unroll
        for (int nt = 0; nt < 8; ++nt)
#pragma unroll
            for (int j = 0; j < 4; ++j) acc[mt][nt][j] = 0.f;

    const uint32_t Xaddr = (uint32_t)__cvta_generic_to_shared(Xh);
    const uint32_t Waddr = (uint32_t)__cvta_generic_to_shared(Wh);
    const uint32_t xbase = Xaddr +
        (((uint32_t)(wm * 32 + (lane & 15)) * XSTR + ((lane >> 4) << 3)) << 1);
    const uint32_t wbase = Waddr +
        (((uint32_t)(wn * 64 + (lane & 7) + ((lane >> 4) << 3)) * XSTR +
          (((lane >> 3) & 1) << 3)) << 1);

#pragma unroll
    for (int ks = 0; ks < 8; ++ks) {
        const int ko = ks * 16;
        uint32_t a[2][4];
#pragma unroll
        for (int mt = 0; mt < 2; ++mt)
            ldsm_x4(a[mt], xbase + (((uint32_t)(mt * 16) * XSTR + ko) << 1));
        uint32_t b[8][2];
#pragma unroll
        for (int p = 0; p < 4; ++p) {
            uint32_t rr[4];
            ldsm_x4(rr, wbase + (((uint32_t)(p * 16) * XSTR + ko) << 1));
            b[2 * p][0] = rr[0]; b[2 * p][1] = rr[1];
            b[2 * p + 1][0] = rr[2]; b[2 * p + 1][1] = rr[3];
        }
#pragma unroll
        for (int mt = 0; mt < 2; ++mt)
#pragma unroll
            for (int nt = 0; nt < 8; ++nt)
                mma_f16(acc[mt][nt], a[mt], b[nt]);
    }

    const int g = lane >> 2;
    const int c = lane & 3;
#pragma unroll
    for (int mt = 0; mt < 2; ++mt) {
        long row0 = rowbase + wm * 32 + mt * 16 + g;
        long row1 = row0 + 8;
        bool ok0 = row0 < ROWS_TOTAL;
        bool ok1 = row1 < ROWS_TOTAL;
#pragma unroll
        for (int nt = 0; nt < 8; ++nt) {
            int f = wn * 64 + nt * 8 + 2 * c;
            if (ok0)
                *(__half2*)(g_support + row0 * FD + f) =
                    __float22half2_rn(make_float2(acc[mt][nt][0], acc[mt][nt][1]));
            if (ok1)
                *(__half2*)(g_support + row1 * FD + f) =
                    __float22half2_rn(make_float2(acc[mt][nt][2], acc[mt][nt][3]));
        }
    }
}

// ======================= SPMM + ReLU (software-pipelined) ====================
// warp per row; lanes 0-15 ch0, lanes 16-31 ch1; lane owns 8 f cols.
// Indices AND gathers for iteration t+1 are issued during iteration t's FMA,
// removing the 2-hop LDG(index)->LDG(gather) chain from the critical path.
__global__ __launch_bounds__(256, 3) void spmm_kernel(float* __restrict__ out) {
    if (blockIdx.x == 0 && threadIdx.x < NCHUNK)
        g_scanstate[threadIdx.x] = 0ULL;   // reset for next graph replay

    const int lane = threadIdx.x & 31;
    const int row = blockIdx.x * 8 + (threadIdx.x >> 5);
    if (row >= NNODES) return;
    const int k   = lane >> 4;
    const int fo  = (lane & 15) << 3;
    const int s = g_rowstart[row];
    const int e = g_rowstart[row + 1];
    const __half* __restrict__ sup = g_support + (size_t)k * NNODES * FD + fo;

    float acc[8], accb[8];
#pragma unroll
    for (int j = 0; j < 8; ++j) { acc[j] = 0.f; accb[j] = 0.f; }

    int i = s;
    int2 cv0, cv1, cv2, cv3;
    uint4 p0, p1, p2, p3;
    if (i + 3 < e) {
        cv0 = __ldg(&g_csr[i]);
        cv1 = __ldg(&g_csr[i + 1]);
        cv2 = __ldg(&g_csr[i + 2]);
        cv3 = __ldg(&g_csr[i + 3]);
        p0 = __ldg((const uint4*)(sup + (size_t)cv0.x * FD));
        p1 = __ldg((const uint4*)(sup + (size_t)cv1.x * FD));
        p2 = __ldg((const uint4*)(sup + (size_t)cv2.x * FD));
        p3 = __ldg((const uint4*)(sup + (size_t)cv3.x * FD));
    }
    while (i + 3 < e) {
        const int inext = i + 4;
        const bool more = (inext + 3 < e);
        int2 n0, n1, n2, n3;
        uint4 q0, q1, q2, q3;
        if (more) {
            n0 = __ldg(&g_csr[inext]);
            n1 = __ldg(&g_csr[inext + 1]);
            n2 = __ldg(&g_csr[inext + 2]);
            n3 = __ldg(&g_csr[inext + 3]);
            q0 = __ldg((const uint4*)(sup + (size_t)n0.x * FD));
            q1 = __ldg((const uint4*)(sup + (size_t)n1.x * FD));
            q2 = __ldg((const uint4*)(sup + (size_t)n2.x * FD));
            q3 = __ldg((const uint4*)(sup + (size_t)n3.x * FD));
        }
        const float v0 = __int_as_float(cv0.y);
        const float v1 = __int_as_float(cv1.y);
        const float v2 = __int_as_float(cv2.y);
        const float v3 = __int_as_float(cv3.y);
        const __half2* h0 = (const __half2*)&p0;
        const __half2* h1 = (const __half2*)&p1;
        const __half2* h2 = (const __half2*)&p2;
        const __half2* h3 = (const __half2*)&p3;
#pragma unroll
        for (int j = 0; j < 4; ++j) {
            float2 f0 = __half22float2(h0[j]);
            float2 f1 = __half22float2(h1[j]);
            float2 f2 = __half22float2(h2[j]);
            float2 f3 = __half22float2(h3[j]);
            acc[2 * j + 0]  = fmaf(v0, f0.x, acc[2 * j + 0]);
            acc[2 * j + 1]  = fmaf(v0, f0.y, acc[2 * j + 1]);
            accb[2 * j + 0] = fmaf(v1, f1.x, accb[2 * j + 0]);
            accb[2 * j + 1] = fmaf(v1, f1.y, accb[2 * j + 1]);
            acc[2 * j + 0]  = fmaf(v2, f2.x, acc[2 * j + 0]);
            acc[2 * j + 1]  = fmaf(v2, f2.y, acc[2 * j + 1]);
            accb[2 * j + 0] = fmaf(v3, f3.x, accb[2 * j + 0]);
            accb[2 * j + 1] = fmaf(v3, f3.y, accb[2 * j + 1]);
        }
        i = inext;
        cv0 = n0; cv1 = n1; cv2 = n2; cv3 = n3;
        p0 = q0; p1 = q1; p2 = q2; p3 = q3;
    }
    for (; i < e; ++i) {
        int2 cv = __ldg(&g_csr[i]);
        float v = __int_as_float(cv.y);
        uint4 p = __ldg((const uint4*)(sup + (size_t)cv.x * FD));
        const __half2* h = (const __half2*)&p;
#pragma unroll
        for (int j = 0; j < 4; ++j) {
            float2 f = __half22float2(h[j]);
            acc[2 * j + 0] = fmaf(v, f.x, acc[2 * j + 0]);
            acc[2 * j + 1] = fmaf(v, f.y, acc[2 * j + 1]);
        }
    }

    float* dst = out + ((size_t)k * NNODES + row) * FD + fo;
    float4 r0 = make_float4(fmaxf(acc[0] + accb[0], 0.f),
                            fmaxf(acc[1] + accb[1], 0.f),
                            fmaxf(acc[2] + accb[2], 0.f),
                            fmaxf(acc[3] + accb[3], 0.f));
    float4 r1 = make_float4(fmaxf(acc[4] + accb[4], 0.f),
                            fmaxf(acc[5] + accb[5], 0.f),
                            fmaxf(acc[6] + accb[6], 0.f),
                            fmaxf(acc[7] + accb[7], 0.f));
    *(float4*)(dst + 0) = r0;
    *(float4*)(dst + 4) = r1;
}

// ======================= launch =============================================
extern "C" void kernel_launch(void* const* d_in, const int* in_sizes, int n_in,
                              void* d_out, int out_size) {
    const float* x    = (const float*)d_in[0];
    const int*   rows = (const int*)d_in[1];
    const int*   cols = (const int*)d_in[2];
    const float* vals = (const float*)d_in[3];
    const float* w    = (const float*)d_in[4];
    float* out = (float*)d_out;
    const int E = in_sizes[1];

    cudaFuncSetAttribute(gemm_scatter_kernel,
                         cudaFuncAttributeMaxDynamicSharedMemorySize,
                         SMEM_GEMM_BYTES);

    const int ngemm = (ROWS_TOTAL + 127) / 128;   // 1563
    const int nhist = (E + 2047) / 2048;          // 782
    const int nwcv  = (FD * ZD + 1023) / 1024;    // 16

    hist_w_kernel<<<nhist + nwcv, 256>>>(rows, w, E, nhist);
    scan_fused_kernel<<<NCHUNK, 1024>>>(E);
    gemm_scatter_kernel<<<ngemm + nhist, 256, SMEM_GEMM_BYTES>>>(
        x, rows, cols, vals, E, ngemm);
    spmm_kernel<<<(NNODES + 7) / 8, 256>>>(out);
}

// round 16
// speedup vs baseline: 1.1669x; 1.1669x over previous
#include <cuda_runtime.h>
#include <cuda_fp16.h>
#include <cstdint>

#define KCH 2
#define NNODES 100000
#define ZD 128
#define FD 128
#define ROWS_TOTAL (KCH * NNODES)   // 200000
#define EDGES_MAX 1600000
#define NCHUNK ((NNODES + 1023) / 1024)   // 98

// ---------------- scratch (static device globals; zero-initialized) --------
__device__ __half g_support[(size_t)ROWS_TOTAL * FD];  // 51.2 MB (fp16)
__device__ __half g_wh[FD * ZD];                       // W^T fp16 [f][k]
__device__ int   g_count[NNODES];                      // starts 0; scan resets
__device__ int   g_rowstart[NNODES + 1];
__device__ int   g_cursor[NNODES];
__device__ unsigned long long g_scanstate[NCHUNK];     // starts 0; spmm resets
__device__ int2  g_csr[EDGES_MAX];                     // (col, val bits)

// ======================= hist (ILP-8) + W convert ===========================
__global__ __launch_bounds__(256) void hist_w_kernel(
    const int* __restrict__ rows, const float* __restrict__ w, int E, int nhist) {
    const int tid = threadIdx.x;
    if (blockIdx.x >= nhist) {
        int base = ((blockIdx.x - nhist) * 256 + tid) * 4;
#pragma unroll
        for (int j = 0; j < 4; ++j) {
            int i = base + j;
            if (i < FD * ZD) {
                int f = i >> 7, k = i & 127;
                g_wh[i] = __float2half_rn(w[k * FD + f]);   // g_wh[f][k]=W[k][f]
            }
        }
        return;
    }
    const int e = (blockIdx.x * 256 + tid) * 8;
    if (e + 7 < E) {
        int4 r0 = *(const int4*)(rows + e);
        int4 r1 = *(const int4*)(rows + e + 4);
        atomicAdd(&g_count[r0.x], 1);
        atomicAdd(&g_count[r0.y], 1);
        atomicAdd(&g_count[r0.z], 1);
        atomicAdd(&g_count[r0.w], 1);
        atomicAdd(&g_count[r1.x], 1);
        atomicAdd(&g_count[r1.y], 1);
        atomicAdd(&g_count[r1.z], 1);
        atomicAdd(&g_count[r1.w], 1);
    } else {
        for (int j = e; j < E; ++j) atomicAdd(&g_count[rows[j]], 1);
    }
}

// fused scan: per-chunk inclusive scan + single-wave lookback; resets g_count
__global__ __launch_bounds__(1024) void scan_fused_kernel(int E) {
    __shared__ int s[1024];
    __shared__ int s_pref;
    const int t = threadIdx.x;
    const int b = blockIdx.x;
    const int idx = b * 1024 + t;
    const int v = (idx < NNODES) ? g_count[idx] : 0;
    s[t] = v;
    __syncthreads();
#pragma unroll
    for (int off = 1; off < 1024; off <<= 1) {
        int add = (t >= off) ? s[t - off] : 0;
        __syncthreads();
        s[t] += add;
        __syncthreads();
    }
    const int incl = s[t];
    if (t == 1023)
        atomicExch(&g_scanstate[b], (1ULL << 63) | (unsigned long long)s[1023]);

    if (t < 32) {
        unsigned int partial = 0;
        for (int base = 0; base < b; base += 32) {
            int j = base + t;
            unsigned int tot = 0;
            if (j < b) {
                unsigned long long w;
                do { w = atomicAdd(&g_scanstate[j], 0ULL); } while (!(w >> 63));
                tot = (unsigned int)w;
            }
            partial += tot;
        }
#pragma unroll
        for (int o = 16; o > 0; o >>= 1)
            partial += __shfl_down_sync(0xFFFFFFFFu, partial, o);
        if (t == 0) s_pref = (int)partial;
    }
    __syncthreads();
    const int excl = s_pref + incl - v;
    if (idx < NNODES) {
        g_rowstart[idx] = excl;
        g_cursor[idx]   = excl;
        g_count[idx]    = 0;    // reset for next graph replay
    }
    if (b == NCHUNK - 1 && t == 0) g_rowstart[NNODES] = E;
}

// ======================= fused GEMM + scatter ================================
#define XSTR 136
#define SMEM_GEMM_BYTES (2 * 128 * XSTR * 2)   // 69632

static __device__ __forceinline__ void ldsm_x4(uint32_t* r, uint32_t addr) {
    asm volatile("ldmatrix.sync.aligned.m8n8.x4.shared.b16 {%0,%1,%2,%3}, [%4];"
                 : "=r"(r[0]), "=r"(r[1]), "=r"(r[2]), "=r"(r[3]) : "r"(addr));
}

static __device__ __forceinline__ void mma_f16(float* d, const uint32_t* a,
                                               const uint32_t* b) {
    asm volatile(
        "mma.sync.aligned.m16n8k16.row.col.f32.f16.f16.f32 "
        "{%0,%1,%2,%3}, {%4,%5,%6,%7}, {%8,%9}, {%0,%1,%2,%3};\n"
        : "+f"(d[0]), "+f"(d[1]), "+f"(d[2]), "+f"(d[3])
        : "r"(a[0]), "r"(a[1]), "r"(a[2]), "r"(a[3]), "r"(b[0]), "r"(b[1]));
}

__global__ __launch_bounds__(256, 2) void gemm_scatter_kernel(
    const float* __restrict__ x,
    const int* __restrict__ rows, const int* __restrict__ cols,
    const float* __restrict__ vals, int E, int ngemm) {
    extern __shared__ __half smh[];
    const int tid = threadIdx.x;

    if (blockIdx.x >= ngemm) {
        // ---------------- scatter path (ILP-8) ----------------
        const int e = ((blockIdx.x - ngemm) * 256 + tid) * 8;
        if (e + 7 < E) {
            int4 r0 = *(const int4*)(rows + e);
            int4 r1 = *(const int4*)(rows + e + 4);
            int4 c0 = *(const int4*)(cols + e);
            int4 c1 = *(const int4*)(cols + e + 4);
            float4 v0 = *(const float4*)(vals + e);
            float4 v1 = *(const float4*)(vals + e + 4);
            int p0 = atomicAdd(&g_cursor[r0.x], 1);
            int p1 = atomicAdd(&g_cursor[r0.y], 1);
            int p2 = atomicAdd(&g_cursor[r0.z], 1);
            int p3 = atomicAdd(&g_cursor[r0.w], 1);
            int p4 = atomicAdd(&g_cursor[r1.x], 1);
            int p5 = atomicAdd(&g_cursor[r1.y], 1);
            int p6 = atomicAdd(&g_cursor[r1.z], 1);
            int p7 = atomicAdd(&g_cursor[r1.w], 1);
            g_csr[p0] = make_int2(c0.x, __float_as_int(v0.x));
            g_csr[p1] = make_int2(c0.y, __float_as_int(v0.y));
            g_csr[p2] = make_int2(c0.z, __float_as_int(v0.z));
            g_csr[p3] = make_int2(c0.w, __float_as_int(v0.w));
            g_csr[p4] = make_int2(c1.x, __float_as_int(v1.x));
            g_csr[p5] = make_int2(c1.y, __float_as_int(v1.y));
            g_csr[p6] = make_int2(c1.z, __float_as_int(v1.z));
            g_csr[p7] = make_int2(c1.w, __float_as_int(v1.w));
        } else {
            for (int j = e; j < E; ++j) {
                int p = atomicAdd(&g_cursor[rows[j]], 1);
                g_csr[p] = make_int2(cols[j], __float_as_int(vals[j]));
            }
        }
        return;
    }

    // ---------------- GEMM path ----------------
    __half* Xh = smh;                    // [128][XSTR]
    __half* Wh = smh + 128 * XSTR;       // [f][XSTR]
    const int lane = tid & 31;
    const int wid = tid >> 5;
    const long rowbase = (long)blockIdx.x * 128;

#pragma unroll
    for (int it = 0; it < 16; ++it) {
        int id4 = tid + it * 256;
        int rr = id4 >> 5;
        int q = (id4 & 31) << 2;
        long grow = rowbase + rr;
        float4 vv = make_float4(0.f, 0.f, 0.f, 0.f);
        if (grow < ROWS_TOTAL) vv = *(const float4*)(x + grow * ZD + q);
        __half2* dst = (__half2*)(Xh + rr * XSTR + q);
        dst[0] = __floats2half2_rn(vv.x, vv.y);
        dst[1] = __floats2half2_rn(vv.z, vv.w);
    }
#pragma unroll
    for (int it = 0; it < 8; ++it) {
        int idx = tid + it * 256;
        int f = idx >> 4;
        int seg = (idx & 15) << 3;
        *(uint4*)(Wh + f * XSTR + seg) = *(const uint4*)(g_wh + f * ZD + seg);
    }
    __syncthreads();

    const int wm = wid >> 1;
    const int wn = wid & 1;

    float acc[2][8][4];
#pragma unroll
    for (int mt = 0; mt < 2; ++mt)
#pragma unroll
        for (int nt = 0; nt < 8; ++nt)
#pragma unroll
            for (int j = 0; j < 4; ++j) acc[mt][nt][j] = 0.f;

    const uint32_t Xaddr = (uint32_t)__cvta_generic_to_shared(Xh);
    const uint32_t Waddr = (uint32_t)__cvta_generic_to_shared(Wh);
    const uint32_t xbase = Xaddr +
        (((uint32_t)(wm * 32 + (lane & 15)) * XSTR + ((lane >> 4) << 3)) << 1);
    const uint32_t wbase = Waddr +
        (((uint32_t)(wn * 64 + (lane & 7) + ((lane >> 4) << 3)) * XSTR +
          (((lane >> 3) & 1) << 3)) << 1);

#pragma unroll
    for (int ks = 0; ks < 8; ++ks) {
        const int ko = ks * 16;
        uint32_t a[2][4];
#pragma unroll
        for (int mt = 0; mt < 2; ++mt)
            ldsm_x4(a[mt], xbase + (((uint32_t)(mt * 16) * XSTR + ko) << 1));
        uint32_t b[8][2];
#pragma unroll
        for (int p = 0; p < 4; ++p) {
            uint32_t rr[4];
            ldsm_x4(rr, wbase + (((uint32_t)(p * 16) * XSTR + ko) << 1));
            b[2 * p][0] = rr[0]; b[2 * p][1] = rr[1];
            b[2 * p + 1][0] = rr[2]; b[2 * p + 1][1] = rr[3];
        }
#pragma unroll
        for (int mt = 0; mt < 2; ++mt)
#pragma unroll
            for (int nt = 0; nt < 8; ++nt)
                mma_f16(acc[mt][nt], a[mt], b[nt]);
    }

    const int g = lane >> 2;
    const int c = lane & 3;
#pragma unroll
    for (int mt = 0; mt < 2; ++mt) {
        long row0 = rowbase + wm * 32 + mt * 16 + g;
        long row1 = row0 + 8;
        bool ok0 = row0 < ROWS_TOTAL;
        bool ok1 = row1 < ROWS_TOTAL;
#pragma unroll
        for (int nt = 0; nt < 8; ++nt) {
            int f = wn * 64 + nt * 8 + 2 * c;
            if (ok0)
                *(__half2*)(g_support + row0 * FD + f) =
                    __float22half2_rn(make_float2(acc[mt][nt][0], acc[mt][nt][1]));
            if (ok1)
                *(__half2*)(g_support + row1 * FD + f) =
                    __float22half2_rn(make_float2(acc[mt][nt][2], acc[mt][nt][3]));
        }
    }
}

// ======================= SPMM + ReLU (index-prefetch only) ===================
// warp per row; lanes 0-15 ch0, lanes 16-31 ch1; lane owns 8 f cols; ILP-4.
// Only the 4 int2 indices for iteration t+1 are prefetched (cheap in regs);
// gathers stay in-iteration so occupancy stays high.
__global__ __launch_bounds__(256, 4) void spmm_kernel(float* __restrict__ out) {
    if (blockIdx.x == 0 && threadIdx.x < NCHUNK)
        g_scanstate[threadIdx.x] = 0ULL;   // reset for next graph replay

    const int lane = threadIdx.x & 31;
    const int row = blockIdx.x * 8 + (threadIdx.x >> 5);
    if (row >= NNODES) return;
    const int k   = lane >> 4;
    const int fo  = (lane & 15) << 3;
    const int s = g_rowstart[row];
    const int e = g_rowstart[row + 1];
    const __half* __restrict__ sup = g_support + (size_t)k * NNODES * FD + fo;

    float acc[8], accb[8];
#pragma unroll
    for (int j = 0; j < 8; ++j) { acc[j] = 0.f; accb[j] = 0.f; }

    int i = s;
    int2 cv0, cv1, cv2, cv3;
    if (i + 3 < e) {
        cv0 = __ldg(&g_csr[i]);
        cv1 = __ldg(&g_csr[i + 1]);
        cv2 = __ldg(&g_csr[i + 2]);
        cv3 = __ldg(&g_csr[i + 3]);
    }
    while (i + 3 < e) {
        // gathers for the current quad (indices already resident)
        uint4 p0 = __ldg((const uint4*)(sup + (size_t)cv0.x * FD));
        uint4 p1 = __ldg((const uint4*)(sup + (size_t)cv1.x * FD));
        uint4 p2 = __ldg((const uint4*)(sup + (size_t)cv2.x * FD));
        uint4 p3 = __ldg((const uint4*)(sup + (size_t)cv3.x * FD));
        const float v0 = __int_as_float(cv0.y);
        const float v1 = __int_as_float(cv1.y);
        const float v2 = __int_as_float(cv2.y);
        const float v3 = __int_as_float(cv3.y);
        // prefetch next quad's indices while gathers are in flight
        const int inext = i + 4;
        if (inext + 3 < e) {
            cv0 = __ldg(&g_csr[inext]);
            cv1 = __ldg(&g_csr[inext + 1]);
            cv2 = __ldg(&g_csr[inext + 2]);
            cv3 = __ldg(&g_csr[inext + 3]);
        }
        const __half2* h0 = (const __half2*)&p0;
        const __half2* h1 = (const __half2*)&p1;
        const __half2* h2 = (const __half2*)&p2;
        const __half2* h3 = (const __half2*)&p3;
#pragma unroll
        for (int j = 0; j < 4; ++j) {
            float2 f0 = __half22float2(h0[j]);
            float2 f1 = __half22float2(h1[j]);
            float2 f2 = __half22float2(h2[j]);
            float2 f3 = __half22float2(h3[j]);
            acc[2 * j + 0]  = fmaf(v0, f0.x, acc[2 * j + 0]);
            acc[2 * j + 1]  = fmaf(v0, f0.y, acc[2 * j + 1]);
            accb[2 * j + 0] = fmaf(v1, f1.x, accb[2 * j + 0]);
            accb[2 * j + 1] = fmaf(v1, f1.y, accb[2 * j + 1]);
            acc[2 * j + 0]  = fmaf(v2, f2.x, acc[2 * j + 0]);
            acc[2 * j + 1]  = fmaf(v2, f2.y, acc[2 * j + 1]);
            accb[2 * j + 0] = fmaf(v3, f3.x, accb[2 * j + 0]);
            accb[2 * j + 1] = fmaf(v3, f3.y, accb[2 * j + 1]);
        }
        i = inext;
    }
    for (; i < e; ++i) {
        int2 cv = __ldg(&g_csr[i]);
        float v = __int_as_float(cv.y);
        uint4 p = __ldg((const uint4*)(sup + (size_t)cv.x * FD));
        const __half2* h = (const __half2*)&p;
#pragma unroll
        for (int j = 0; j < 4; ++j) {
            float2 f = __half22float2(h[j]);
            acc[2 * j + 0] = fmaf(v, f.x, acc[2 * j + 0]);
            acc[2 * j + 1] = fmaf(v, f.y, acc[2 * j + 1]);
        }
    }

    float* dst = out + ((size_t)k * NNODES + row) * FD + fo;
    float4 r0 = make_float4(fmaxf(acc[0] + accb[0], 0.f),
                            fmaxf(acc[1] + accb[1], 0.f),
                            fmaxf(acc[2] + accb[2], 0.f),
                            fmaxf(acc[3] + accb[3], 0.f));
    float4 r1 = make_float4(fmaxf(acc[4] + accb[4], 0.f),
                            fmaxf(acc[5] + accb[5], 0.f),
                            fmaxf(acc[6] + accb[6], 0.f),
                            fmaxf(acc[7] + accb[7], 0.f));
    *(float4*)(dst + 0) = r0;
    *(float4*)(dst + 4) = r1;
}

// ======================= launch =============================================
extern "C" void kernel_launch(void* const* d_in, const int* in_sizes, int n_in,
                              void* d_out, int out_size) {
    const float* x    = (const float*)d_in[0];
    const int*   rows = (const int*)d_in[1];
    const int*   cols = (const int*)d_in[2];
    const float* vals = (const float*)d_in[3];
    const float* w    = (const float*)d_in[4];
    float* out = (float*)d_out;
    const int E = in_sizes[1];

    cudaFuncSetAttribute(gemm_scatter_kernel,
                         cudaFuncAttributeMaxDynamicSharedMemorySize,
                         SMEM_GEMM_BYTES);

    const int ngemm = (ROWS_TOTAL + 127) / 128;   // 1563
    const int nhist = (E + 2047) / 2048;          // 782
    const int nwcv  = (FD * ZD + 1023) / 1024;    // 16

    hist_w_kernel<<<nhist + nwcv, 256>>>(rows, w, E, nhist);
    scan_fused_kernel<<<NCHUNK, 1024>>>(E);
    gemm_scatter_kernel<<<ngemm + nhist, 256, SMEM_GEMM_BYTES>>>(
        x, rows, cols, vals, E, ngemm);
    spmm_kernel<<<(NNODES + 7) / 8, 256>>>(out);
}